// round 2
// baseline (speedup 1.0000x reference)
#include <cuda_runtime.h>
#include <stdint.h>

#define BB 2
#define NN 16384
#define MM 4096
#define CC 32
#define DD 64
#define HH 32
#define KK 16
#define EPSV 1e-5f
#define NQ (BB*MM)   // 8192

// ---------------- scratch (__device__ globals; no allocations allowed) ----------------
__device__ float g_featsT[BB*NN*CC];          // [B,N,C] transposed feats (4MB)
__device__ int   g_knn[NQ*KK];                // knn indices
__device__ float g_comb[(size_t)NQ*KK*DD];    // pre-BN combined: [q][k][64] (feat 0:32, pos 32:64)
__device__ float g_sc1[NQ*DD];                // pre-BN shortcut1
__device__ float g_sc2[NQ*DD];                // pre-BN shortcut2
__device__ float g_outp[NQ*DD];               // pre-BN pooled@W_out
// stats: [0:32) pos s1 [32:64) pos s2 [64:96) feat s1 [96:128) feat s2
// [128:192) sc1 s1 [192:256) sc1 s2 [256:320) sc2 s1 [320:384) sc2 s2 [384:448) out s1 [448:512) out s2
__device__ float g_stats[512];
// bn coeffs: [0:64) a_comb [64:128) b_comb [128:192) a_sc1 [192:256) b_sc1
// [256:320) a_sc2 [320:384) b_sc2 [384:448) a_out [448:512) b_out
__device__ float g_bn[512];

__device__ __forceinline__ unsigned long long umin64(unsigned long long a, unsigned long long b) {
    return a < b ? a : b;
}

// ---------------- K0: zero stats, write xyz_ds + sample_idx to output ----------------
__global__ void k_init(const float* __restrict__ xyz, const int* __restrict__ sidx,
                       float* __restrict__ out) {
    int t = blockIdx.x * 256 + threadIdx.x;
    if (t < 512) g_stats[t] = 0.f;
    if (t < NQ) {
        int b = t >> 12;          // t / 4096
        int n = sidx[t];
        const float* p = xyz + ((size_t)b * NN + n) * 3;
        out[t * 3 + 0] = p[0];
        out[t * 3 + 1] = p[1];
        out[t * 3 + 2] = p[2];
        out[24576 + 524288 + t] = (float)n;   // sample_idx as float
    }
}

// ---------------- K0b: transpose feats [B,C,N] -> [B,N,C] ----------------
__global__ void k_transpose(const float* __restrict__ feats) {
    __shared__ float tile[32][33];
    int b = blockIdx.y;
    int n0 = blockIdx.x * 32;
    int tx = threadIdx.x, ty = threadIdx.y;
    tile[ty][tx] = feats[((size_t)b * CC + ty) * NN + n0 + tx];
    __syncthreads();
    g_featsT[((size_t)b * NN + n0 + ty) * CC + tx] = tile[tx][ty];
}

// ---------------- K1: KNN (warp per query, smem xyz tiles) ----------------
#define TS 2048
__global__ __launch_bounds__(512) void k_knn(const float* __restrict__ xyz,
                                             const int* __restrict__ sidx) {
    __shared__ float4 tile[TS];
    int warp = threadIdx.x >> 5, lane = threadIdx.x & 31;
    int q = blockIdx.x * 16 + warp;           // 0..8191
    int b = q >> 12;
    const float* xb = xyz + (size_t)b * NN * 3;
    int sn = sidx[q];
    float qx = xb[sn * 3 + 0], qy = xb[sn * 3 + 1], qz = xb[sn * 3 + 2];

    unsigned long long keys[KK];
#pragma unroll
    for (int i = 0; i < KK; i++) keys[i] = 0xFFFFFFFFFFFFFFFFull;
    unsigned long long worst = 0xFFFFFFFFFFFFFFFFull;
    int wpos = 0;

    for (int t0 = 0; t0 < NN; t0 += TS) {
        __syncthreads();
        for (int i = threadIdx.x; i < TS; i += 512) {
            const float* p = xb + (size_t)(t0 + i) * 3;
            tile[i] = make_float4(p[0], p[1], p[2], 0.f);
        }
        __syncthreads();
        for (int i = lane; i < TS; i += 32) {
            float4 p = tile[i];
            float dx = qx - p.x, dy = qy - p.y, dz = qz - p.z;
            float d2 = dx * dx + dy * dy + dz * dz;
            unsigned long long key =
                ((unsigned long long)__float_as_uint(d2) << 32) | (unsigned)(t0 + i);
            if (key < worst) {
#pragma unroll
                for (int s = 0; s < KK; s++) if (s == wpos) keys[s] = key;
                worst = keys[0]; wpos = 0;
#pragma unroll
                for (int s = 1; s < KK; s++)
                    if (keys[s] > worst) { worst = keys[s]; wpos = s; }
            }
        }
    }
    // merge 32 thread-local top-16 lists -> warp top-16
    for (int r = 0; r < KK; r++) {
        unsigned long long lmin = keys[0];
#pragma unroll
        for (int s = 1; s < KK; s++) lmin = umin64(lmin, keys[s]);
        unsigned long long wmin = lmin;
#pragma unroll
        for (int off = 16; off; off >>= 1)
            wmin = umin64(wmin, __shfl_xor_sync(0xffffffffu, wmin, off));
        if (lmin == wmin) {
#pragma unroll
            for (int s = 0; s < KK; s++)
                if (keys[s] == wmin) keys[s] = 0xFFFFFFFFFFFFFFFFull;
        }
        if (lane == 0) g_knn[q * KK + r] = (int)(wmin & 0xFFFFFFFFull);
    }
}

// ---------------- K2: gather + pos/feat linear + shortcuts + stats ----------------
__global__ __launch_bounds__(256) void k_stage2(
    const float* __restrict__ xyz, const int* __restrict__ sidx,
    const float* __restrict__ Wp, const float* __restrict__ bp,
    const float* __restrict__ Wf, const float* __restrict__ bf,
    const float* __restrict__ Wsc1, const float* __restrict__ Wsc2) {
    __shared__ float nf[8][KK][CC];
    __shared__ float posf[8][KK][10];
    __shared__ float mf[8][CC];
    __shared__ float cfs[8][CC];
    __shared__ int   nidx[8][KK];
    __shared__ float acc[384];

    int tid = threadIdx.x;
    for (int i = tid; i < 384; i += 256) acc[i] = 0.f;   // FIX: strided init (blockDim=256 < 384)
    __syncthreads();

    int warp = tid >> 5, lane = tid & 31;
    int q = blockIdx.x * 8 + warp;
    int b = q >> 12;
    const float* ftb = g_featsT + (size_t)b * NN * CC;
    const float* xb  = xyz + (size_t)b * NN * 3;
    int sn = sidx[q];
    float qx = xb[sn * 3 + 0], qy = xb[sn * 3 + 1], qz = xb[sn * 3 + 2];

    if (lane < KK) nidx[warp][lane] = g_knn[q * KK + lane];
    __syncwarp();
    for (int k = 0; k < KK; k++) {
        int n = nidx[warp][k];
        nf[warp][k][lane] = ftb[n * CC + lane];
    }
    if (lane < KK) {
        int n = nidx[warp][lane];
        float px = xb[n * 3 + 0], py = xb[n * 3 + 1], pz = xb[n * 3 + 2];
        float rx = qx - px, ry = qy - py, rz = qz - pz;
        float dist = sqrtf(rx * rx + ry * ry + rz * rz);
        float* pf = posf[warp][lane];
        pf[0] = qx; pf[1] = qy; pf[2] = qz;
        pf[3] = px; pf[4] = py; pf[5] = pz;
        pf[6] = rx; pf[7] = ry; pf[8] = rz; pf[9] = dist;
    }
    cfs[warp][lane] = ftb[sn * CC + lane];
    __syncwarp();

    float* cb = g_comb + (size_t)q * KK * DD;

    // positional linear: lane = channel h (0..31)
    {
        float wp[10];
#pragma unroll
        for (int j = 0; j < 10; j++) wp[j] = Wp[j * HH + lane];
        float bias = bp[lane];
        float s1 = 0.f, s2 = 0.f;
        for (int k = 0; k < KK; k++) {
            float v = bias;
#pragma unroll
            for (int j = 0; j < 10; j++) v = fmaf(posf[warp][k][j], wp[j], v);
            cb[k * DD + 32 + lane] = v;
            s1 += v; s2 = fmaf(v, v, s2);
        }
        atomicAdd(&acc[0 + lane], s1);
        atomicAdd(&acc[32 + lane], s2);
    }
    // feature linear
    {
        float wf[CC];
#pragma unroll
        for (int c = 0; c < CC; c++) wf[c] = Wf[c * HH + lane];
        float bias = bf[lane];
        float s1 = 0.f, s2 = 0.f;
        for (int k = 0; k < KK; k++) {
            float v = bias;
#pragma unroll
            for (int c = 0; c < CC; c++) v = fmaf(nf[warp][k][c], wf[c], v);
            cb[k * DD + lane] = v;
            s1 += v; s2 = fmaf(v, v, s2);
        }
        atomicAdd(&acc[64 + lane], s1);
        atomicAdd(&acc[96 + lane], s2);
    }
    // mean over K (lane = channel c)
    {
        float mv = 0.f;
#pragma unroll
        for (int k = 0; k < KK; k++) mv += nf[warp][k][lane];
        mf[warp][lane] = mv * (1.f / 16.f);
    }
    __syncwarp();
    // shortcuts: lane handles d = lane and d = lane+32
#pragma unroll
    for (int half = 0; half < 2; half++) {
        int d = lane + half * 32;
        float a1 = 0.f, a2 = 0.f;
#pragma unroll
        for (int c = 0; c < CC; c++) {
            a1 = fmaf(mf[warp][c],  Wsc1[c * DD + d], a1);
            a2 = fmaf(cfs[warp][c], Wsc2[c * DD + d], a2);
        }
        g_sc1[q * DD + d] = a1;
        g_sc2[q * DD + d] = a2;
        atomicAdd(&acc[128 + d], a1);
        atomicAdd(&acc[192 + d], a1 * a1);
        atomicAdd(&acc[256 + d], a2);
        atomicAdd(&acc[320 + d], a2 * a2);
    }
    __syncthreads();
    for (int i = tid; i < 384; i += 256) atomicAdd(&g_stats[i], acc[i]);  // FIX: strided flush
}

// ---------------- K3: finalize BN coeffs for combined / sc1 / sc2 ----------------
__global__ void k_fstats1(const float* __restrict__ gpos, const float* __restrict__ bepos,
                          const float* __restrict__ gfeat, const float* __restrict__ befeat,
                          const float* __restrict__ gsc1, const float* __restrict__ besc1,
                          const float* __restrict__ gsc2, const float* __restrict__ besc2) {
    int d = threadIdx.x;  // 0..63
    float n1 = (float)((size_t)NQ * KK);
    float s1, s2, g, be;
    if (d < 32) { s1 = g_stats[64 + d]; s2 = g_stats[96 + d]; g = gfeat[d]; be = befeat[d]; }
    else { int h = d - 32; s1 = g_stats[h]; s2 = g_stats[32 + h]; g = gpos[h]; be = bepos[h]; }
    float mu = s1 / n1, var = s2 / n1 - mu * mu;
    float a = g * rsqrtf(var + EPSV);
    g_bn[d] = a; g_bn[64 + d] = be - mu * a;

    float n2 = (float)NQ;
    s1 = g_stats[128 + d]; s2 = g_stats[192 + d];
    mu = s1 / n2; var = s2 / n2 - mu * mu;
    a = gsc1[d] * rsqrtf(var + EPSV);
    g_bn[128 + d] = a; g_bn[192 + d] = besc1[d] - mu * a;

    s1 = g_stats[256 + d]; s2 = g_stats[320 + d];
    mu = s1 / n2; var = s2 / n2 - mu * mu;
    a = gsc2[d] * rsqrtf(var + EPSV);
    g_bn[256 + d] = a; g_bn[320 + d] = besc2[d] - mu * a;
}

// ---------------- K4: BN+relu, attention scores, softmax-K, pooling, W_out ----------------
__global__ __launch_bounds__(256) void k_attn(const float* __restrict__ Ws,
                                              const float* __restrict__ Wo) {
    __shared__ float comb[8][KK * DD];
    __shared__ float pool[8][DD];
    __shared__ float acc[128];
    int tid = threadIdx.x;
    if (tid < 128) acc[tid] = 0.f;
    __syncthreads();

    int warp = tid >> 5, lane = tid & 31;
    int q = blockIdx.x * 8 + warp;
    float a0 = g_bn[lane],      b0 = g_bn[64 + lane];
    float a1 = g_bn[lane + 32], b1 = g_bn[64 + lane + 32];
    const float* cp = g_comb + (size_t)q * KK * DD;

    float c0[KK], c1[KK];
#pragma unroll
    for (int k = 0; k < KK; k++) {
        float v0 = fmaxf(fmaf(a0, cp[k * DD + lane],      b0), 0.f);
        float v1 = fmaxf(fmaf(a1, cp[k * DD + lane + 32], b1), 0.f);
        c0[k] = v0; c1[k] = v1;
        comb[warp][k * DD + lane]      = v0;
        comb[warp][k * DD + lane + 32] = v1;
    }
    __syncwarp();

    float s0[KK], s1v[KK];
#pragma unroll
    for (int k = 0; k < KK; k++) { s0[k] = 0.f; s1v[k] = 0.f; }
    for (int dp = 0; dp < DD; dp++) {
        float w0 = Ws[dp * DD + lane];
        float w1 = Ws[dp * DD + lane + 32];
#pragma unroll
        for (int k = 0; k < KK; k++) {
            float cv = comb[warp][k * DD + dp];
            s0[k]  = fmaf(cv, w0, s0[k]);
            s1v[k] = fmaf(cv, w1, s1v[k]);
        }
    }
    // softmax over K per output channel, then pooled
    float p0 = 0.f, p1 = 0.f;
    {
        float mx = s0[0];
#pragma unroll
        for (int k = 1; k < KK; k++) mx = fmaxf(mx, s0[k]);
        float sum = 0.f;
#pragma unroll
        for (int k = 0; k < KK; k++) { float e = __expf(s0[k] - mx); s0[k] = e; sum += e; }
        float inv = 1.f / sum;
#pragma unroll
        for (int k = 0; k < KK; k++) p0 = fmaf(s0[k] * inv, c0[k], p0);
    }
    {
        float mx = s1v[0];
#pragma unroll
        for (int k = 1; k < KK; k++) mx = fmaxf(mx, s1v[k]);
        float sum = 0.f;
#pragma unroll
        for (int k = 0; k < KK; k++) { float e = __expf(s1v[k] - mx); s1v[k] = e; sum += e; }
        float inv = 1.f / sum;
#pragma unroll
        for (int k = 0; k < KK; k++) p1 = fmaf(s1v[k] * inv, c1[k], p1);
    }
    pool[warp][lane] = p0;
    pool[warp][lane + 32] = p1;
    __syncwarp();

    float o0 = 0.f, o1 = 0.f;
    for (int dp = 0; dp < DD; dp++) {
        float pv = pool[warp][dp];
        o0 = fmaf(pv, Wo[dp * DD + lane],      o0);
        o1 = fmaf(pv, Wo[dp * DD + lane + 32], o1);
    }
    g_outp[q * DD + lane] = o0;
    g_outp[q * DD + lane + 32] = o1;
    atomicAdd(&acc[lane], o0);
    atomicAdd(&acc[lane + 32], o1);
    atomicAdd(&acc[64 + lane], o0 * o0);
    atomicAdd(&acc[64 + lane + 32], o1 * o1);
    __syncthreads();
    if (tid < 128) atomicAdd(&g_stats[384 + tid], acc[tid]);
}

// ---------------- K5a: finalize out BN ----------------
__global__ void k_fout(const float* __restrict__ gout, const float* __restrict__ beout) {
    int d = threadIdx.x;
    float n = (float)NQ;
    float s1 = g_stats[384 + d], s2 = g_stats[448 + d];
    float mu = s1 / n, var = s2 / n - mu * mu;
    float a = gout[d] * rsqrtf(var + EPSV);
    g_bn[384 + d] = a; g_bn[448 + d] = beout[d] - mu * a;
}

// ---------------- K5: fused epilogue, write y transposed [B,D,M] ----------------
__global__ void k_final(float* __restrict__ out) {
    int idx = blockIdx.x * 256 + threadIdx.x;     // over B*D*M = 524288
    int m = idx & 4095;
    int d = (idx >> 12) & 63;
    int b = idx >> 18;
    int q = b * MM + m;
    float o  = fmaxf(fmaf(g_bn[384 + d], g_outp[q * DD + d], g_bn[448 + d]), 0.f);
    float v1 = fmaf(g_bn[128 + d], g_sc1[q * DD + d], g_bn[192 + d]);
    float v2 = fmaf(g_bn[256 + d], g_sc2[q * DD + d], g_bn[320 + d]);
    out[24576 + idx] = fmaxf(o + v1 + v2, 0.f);
}

// ---------------- launch ----------------
extern "C" void kernel_launch(void* const* d_in, const int* in_sizes, int n_in,
                              void* d_out, int out_size) {
    const float* xyz    = (const float*)d_in[0];
    const float* feats  = (const float*)d_in[1];
    const int*   sidx   = (const int*)  d_in[2];
    const float* Wpos   = (const float*)d_in[3];
    const float* bpos   = (const float*)d_in[4];
    const float* gpos   = (const float*)d_in[5];
    const float* bepos  = (const float*)d_in[6];
    const float* Wfeat  = (const float*)d_in[7];
    const float* bfeat  = (const float*)d_in[8];
    const float* gfeat  = (const float*)d_in[9];
    const float* befeat = (const float*)d_in[10];
    const float* Wscore = (const float*)d_in[11];
    const float* Wout   = (const float*)d_in[12];
    const float* gout   = (const float*)d_in[13];
    const float* beout  = (const float*)d_in[14];
    const float* Wsc1   = (const float*)d_in[15];
    const float* gsc1   = (const float*)d_in[16];
    const float* besc1  = (const float*)d_in[17];
    const float* Wsc2   = (const float*)d_in[18];
    const float* gsc2   = (const float*)d_in[19];
    const float* besc2  = (const float*)d_in[20];
    float* out = (float*)d_out;

    k_init<<<32, 256>>>(xyz, sidx, out);
    dim3 tb(32, 32);
    k_transpose<<<dim3(NN / 32, BB), tb>>>(feats);
    k_knn<<<NQ / 16, 512>>>(xyz, sidx);
    k_stage2<<<NQ / 8, 256>>>(xyz, sidx, Wpos, bpos, Wfeat, bfeat, Wsc1, Wsc2);
    k_fstats1<<<1, 64>>>(gpos, bepos, gfeat, befeat, gsc1, besc1, gsc2, besc2);
    k_attn<<<NQ / 8, 256>>>(Wscore, Wout);
    k_fout<<<1, 64>>>(gout, beout);
    k_final<<<(BB * DD * MM) / 256, 256>>>(out);
}

// round 3
// speedup vs baseline: 6.1477x; 6.1477x over previous
#include <cuda_runtime.h>
#include <stdint.h>

#define BB 2
#define NN 16384
#define MM 4096
#define CC 32
#define DD 64
#define HH 32
#define KK 16
#define EPSV 1e-5f
#define NQ (BB*MM)   // 8192

// ---------------- scratch (__device__ globals; no allocations allowed) ----------------
__device__ float4 g_xyz4[BB*NN];              // padded xyz for coalesced float4 loads
__device__ float g_featsT[BB*NN*CC];          // [B,N,C] transposed feats (4MB)
__device__ int   g_knn[NQ*KK];                // knn indices
__device__ float g_comb[(size_t)NQ*KK*DD];    // pre-BN combined: [q][k][64] (feat 0:32, pos 32:64)
__device__ float g_sc1[NQ*DD];                // pre-BN shortcut1
__device__ float g_sc2[NQ*DD];                // pre-BN shortcut2
__device__ float g_outp[NQ*DD];               // pre-BN pooled@W_out
// stats layout: see k_fstats1
__device__ float g_stats[512];
__device__ float g_bn[512];

// ---------------- K0: zero stats, write xyz_ds + sample_idx to output ----------------
__global__ void k_init(const float* __restrict__ xyz, const int* __restrict__ sidx,
                       float* __restrict__ out) {
    int t = blockIdx.x * 256 + threadIdx.x;
    if (t < 512) g_stats[t] = 0.f;
    if (t < NQ) {
        int b = t >> 12;
        int n = sidx[t];
        const float* p = xyz + ((size_t)b * NN + n) * 3;
        out[t * 3 + 0] = p[0];
        out[t * 3 + 1] = p[1];
        out[t * 3 + 2] = p[2];
        out[24576 + 524288 + t] = (float)n;   // sample_idx as float
    }
}

// ---------------- K0a: pad xyz into float4 ----------------
__global__ void k_prep(const float* __restrict__ xyz) {
    int t = blockIdx.x * 256 + threadIdx.x;   // over B*N = 32768
    if (t < BB * NN)
        g_xyz4[t] = make_float4(xyz[3 * t], xyz[3 * t + 1], xyz[3 * t + 2], 0.f);
}

// ---------------- K0b: transpose feats [B,C,N] -> [B,N,C] ----------------
__global__ void k_transpose(const float* __restrict__ feats) {
    __shared__ float tile[32][33];
    int b = blockIdx.y;
    int n0 = blockIdx.x * 32;
    int tx = threadIdx.x, ty = threadIdx.y;
    tile[ty][tx] = feats[((size_t)b * CC + ty) * NN + n0 + tx];
    __syncthreads();
    g_featsT[((size_t)b * NN + n0 + ty) * CC + tx] = tile[tx][ty];
}

// ---------------- K1: KNN — warp-distributed sorted top-16 ----------------
// Lanes 0..15 hold the current best-16 (d2 ascending); lane 15's key is the
// warp-wide threshold. Candidates are found via ballot and inserted by a
// shuffle shift. Expected insertions per query ~127 total.
#define TS 2048
__global__ __launch_bounds__(512) void k_knn(const int* __restrict__ sidx) {
    __shared__ float4 tile[TS];
    int warp = threadIdx.x >> 5, lane = threadIdx.x & 31;
    int q = blockIdx.x * 16 + warp;           // 0..8191
    int b = q >> 12;
    const float4* xb = g_xyz4 + (size_t)b * NN;
    int sn = sidx[q];
    float4 qp = xb[sn];
    float qx = qp.x, qy = qp.y, qz = qp.z;

    float bk = 3.402823466e38f;   // sorted list key (lanes 0..15)
    int   bi = 0;                 // sorted list index
    float worst = 3.402823466e38f;

    for (int t0 = 0; t0 < NN; t0 += TS) {
        __syncthreads();
        for (int i = threadIdx.x; i < TS; i += 512)
            tile[i] = xb[t0 + i];
        __syncthreads();
#pragma unroll 4
        for (int i0 = 0; i0 < TS; i0 += 32) {
            int idx = t0 + i0 + lane;
            float4 p = tile[i0 + lane];
            float dx = qx - p.x, dy = qy - p.y, dz = qz - p.z;
            float d2 = fmaf(dx, dx, fmaf(dy, dy, dz * dz));
            unsigned ball = __ballot_sync(0xffffffffu, d2 < worst);
            while (ball) {
                int src = __ffs(ball) - 1;
                ball &= ball - 1;
                float nd = __shfl_sync(0xffffffffu, d2, src);
                int   ni = __shfl_sync(0xffffffffu, idx, src);
                if (nd < worst) {     // uniform: worst may have shrunk
                    float upk = __shfl_up_sync(0xffffffffu, bk, 1);
                    int   upi = __shfl_up_sync(0xffffffffu, bi, 1);
                    unsigned gt = __ballot_sync(0xffffffffu, (lane < KK) && (bk > nd));
                    int fg = __ffs(gt) - 1;
                    if ((lane < KK) && bk > nd) {
                        if (lane == fg) { bk = nd;  bi = ni; }
                        else            { bk = upk; bi = upi; }
                    }
                    worst = __shfl_sync(0xffffffffu, bk, KK - 1);
                }
            }
        }
    }
    if (lane < KK) g_knn[q * KK + lane] = bi;
}

// ---------------- K2: gather + pos/feat linear + shortcuts + stats ----------------
__global__ __launch_bounds__(256) void k_stage2(
    const float* __restrict__ xyz, const int* __restrict__ sidx,
    const float* __restrict__ Wp, const float* __restrict__ bp,
    const float* __restrict__ Wf, const float* __restrict__ bf,
    const float* __restrict__ Wsc1, const float* __restrict__ Wsc2) {
    __shared__ float nf[8][KK][CC];
    __shared__ float posf[8][KK][10];
    __shared__ float mf[8][CC];
    __shared__ float cfs[8][CC];
    __shared__ int   nidx[8][KK];
    __shared__ float acc[384];

    int tid = threadIdx.x;
    for (int i = tid; i < 384; i += 256) acc[i] = 0.f;
    __syncthreads();

    int warp = tid >> 5, lane = tid & 31;
    int q = blockIdx.x * 8 + warp;
    int b = q >> 12;
    const float* ftb = g_featsT + (size_t)b * NN * CC;
    const float4* xb = g_xyz4 + (size_t)b * NN;
    int sn = sidx[q];
    float4 qp = xb[sn];
    float qx = qp.x, qy = qp.y, qz = qp.z;

    if (lane < KK) nidx[warp][lane] = g_knn[q * KK + lane];
    __syncwarp();
    for (int k = 0; k < KK; k++) {
        int n = nidx[warp][k];
        nf[warp][k][lane] = ftb[n * CC + lane];
    }
    if (lane < KK) {
        int n = nidx[warp][lane];
        float4 pp = xb[n];
        float rx = qx - pp.x, ry = qy - pp.y, rz = qz - pp.z;
        float dist = sqrtf(rx * rx + ry * ry + rz * rz);
        float* pf = posf[warp][lane];
        pf[0] = qx; pf[1] = qy; pf[2] = qz;
        pf[3] = pp.x; pf[4] = pp.y; pf[5] = pp.z;
        pf[6] = rx; pf[7] = ry; pf[8] = rz; pf[9] = dist;
    }
    cfs[warp][lane] = ftb[sn * CC + lane];
    __syncwarp();

    float* cb = g_comb + (size_t)q * KK * DD;

    // positional linear: lane = channel h (0..31)
    {
        float wp[10];
#pragma unroll
        for (int j = 0; j < 10; j++) wp[j] = Wp[j * HH + lane];
        float bias = bp[lane];
        float s1 = 0.f, s2 = 0.f;
        for (int k = 0; k < KK; k++) {
            float v = bias;
#pragma unroll
            for (int j = 0; j < 10; j++) v = fmaf(posf[warp][k][j], wp[j], v);
            cb[k * DD + 32 + lane] = v;
            s1 += v; s2 = fmaf(v, v, s2);
        }
        atomicAdd(&acc[0 + lane], s1);
        atomicAdd(&acc[32 + lane], s2);
    }
    // feature linear
    {
        float wf[CC];
#pragma unroll
        for (int c = 0; c < CC; c++) wf[c] = Wf[c * HH + lane];
        float bias = bf[lane];
        float s1 = 0.f, s2 = 0.f;
        for (int k = 0; k < KK; k++) {
            float v = bias;
#pragma unroll
            for (int c = 0; c < CC; c++) v = fmaf(nf[warp][k][c], wf[c], v);
            cb[k * DD + lane] = v;
            s1 += v; s2 = fmaf(v, v, s2);
        }
        atomicAdd(&acc[64 + lane], s1);
        atomicAdd(&acc[96 + lane], s2);
    }
    // mean over K (lane = channel c)
    {
        float mv = 0.f;
#pragma unroll
        for (int k = 0; k < KK; k++) mv += nf[warp][k][lane];
        mf[warp][lane] = mv * (1.f / 16.f);
    }
    __syncwarp();
    // shortcuts: lane handles d = lane and d = lane+32
#pragma unroll
    for (int half = 0; half < 2; half++) {
        int d = lane + half * 32;
        float a1 = 0.f, a2 = 0.f;
#pragma unroll
        for (int c = 0; c < CC; c++) {
            a1 = fmaf(mf[warp][c],  Wsc1[c * DD + d], a1);
            a2 = fmaf(cfs[warp][c], Wsc2[c * DD + d], a2);
        }
        g_sc1[q * DD + d] = a1;
        g_sc2[q * DD + d] = a2;
        atomicAdd(&acc[128 + d], a1);
        atomicAdd(&acc[192 + d], a1 * a1);
        atomicAdd(&acc[256 + d], a2);
        atomicAdd(&acc[320 + d], a2 * a2);
    }
    __syncthreads();
    for (int i = tid; i < 384; i += 256) atomicAdd(&g_stats[i], acc[i]);
}

// ---------------- K3: finalize BN coeffs for combined / sc1 / sc2 ----------------
__global__ void k_fstats1(const float* __restrict__ gpos, const float* __restrict__ bepos,
                          const float* __restrict__ gfeat, const float* __restrict__ befeat,
                          const float* __restrict__ gsc1, const float* __restrict__ besc1,
                          const float* __restrict__ gsc2, const float* __restrict__ besc2) {
    int d = threadIdx.x;  // 0..63
    float n1 = (float)((size_t)NQ * KK);
    float s1, s2, g, be;
    if (d < 32) { s1 = g_stats[64 + d]; s2 = g_stats[96 + d]; g = gfeat[d]; be = befeat[d]; }
    else { int h = d - 32; s1 = g_stats[h]; s2 = g_stats[32 + h]; g = gpos[h]; be = bepos[h]; }
    float mu = s1 / n1, var = s2 / n1 - mu * mu;
    float a = g * rsqrtf(var + EPSV);
    g_bn[d] = a; g_bn[64 + d] = be - mu * a;

    float n2 = (float)NQ;
    s1 = g_stats[128 + d]; s2 = g_stats[192 + d];
    mu = s1 / n2; var = s2 / n2 - mu * mu;
    a = gsc1[d] * rsqrtf(var + EPSV);
    g_bn[128 + d] = a; g_bn[192 + d] = besc1[d] - mu * a;

    s1 = g_stats[256 + d]; s2 = g_stats[320 + d];
    mu = s1 / n2; var = s2 / n2 - mu * mu;
    a = gsc2[d] * rsqrtf(var + EPSV);
    g_bn[256 + d] = a; g_bn[320 + d] = besc2[d] - mu * a;
}

// ---------------- K4: BN+relu, attention scores, softmax-K, pooling, W_out ----------------
__global__ __launch_bounds__(256) void k_attn(const float* __restrict__ Ws,
                                              const float* __restrict__ Wo) {
    __shared__ float comb[8][KK * DD];
    __shared__ float pool[8][DD];
    __shared__ float acc[128];
    int tid = threadIdx.x;
    if (tid < 128) acc[tid] = 0.f;
    __syncthreads();

    int warp = tid >> 5, lane = tid & 31;
    int q = blockIdx.x * 8 + warp;
    float a0 = g_bn[lane],      b0 = g_bn[64 + lane];
    float a1 = g_bn[lane + 32], b1 = g_bn[64 + lane + 32];
    const float* cp = g_comb + (size_t)q * KK * DD;

    float c0[KK], c1[KK];
#pragma unroll
    for (int k = 0; k < KK; k++) {
        float v0 = fmaxf(fmaf(a0, cp[k * DD + lane],      b0), 0.f);
        float v1 = fmaxf(fmaf(a1, cp[k * DD + lane + 32], b1), 0.f);
        c0[k] = v0; c1[k] = v1;
        comb[warp][k * DD + lane]      = v0;
        comb[warp][k * DD + lane + 32] = v1;
    }
    __syncwarp();

    float s0[KK], s1v[KK];
#pragma unroll
    for (int k = 0; k < KK; k++) { s0[k] = 0.f; s1v[k] = 0.f; }
    for (int dp = 0; dp < DD; dp++) {
        float w0 = Ws[dp * DD + lane];
        float w1 = Ws[dp * DD + lane + 32];
#pragma unroll
        for (int k = 0; k < KK; k++) {
            float cv = comb[warp][k * DD + dp];
            s0[k]  = fmaf(cv, w0, s0[k]);
            s1v[k] = fmaf(cv, w1, s1v[k]);
        }
    }
    // softmax over K per output channel, then pooled
    float p0 = 0.f, p1 = 0.f;
    {
        float mx = s0[0];
#pragma unroll
        for (int k = 1; k < KK; k++) mx = fmaxf(mx, s0[k]);
        float sum = 0.f;
#pragma unroll
        for (int k = 0; k < KK; k++) { float e = __expf(s0[k] - mx); s0[k] = e; sum += e; }
        float inv = 1.f / sum;
#pragma unroll
        for (int k = 0; k < KK; k++) p0 = fmaf(s0[k] * inv, c0[k], p0);
    }
    {
        float mx = s1v[0];
#pragma unroll
        for (int k = 1; k < KK; k++) mx = fmaxf(mx, s1v[k]);
        float sum = 0.f;
#pragma unroll
        for (int k = 0; k < KK; k++) { float e = __expf(s1v[k] - mx); s1v[k] = e; sum += e; }
        float inv = 1.f / sum;
#pragma unroll
        for (int k = 0; k < KK; k++) p1 = fmaf(s1v[k] * inv, c1[k], p1);
    }
    pool[warp][lane] = p0;
    pool[warp][lane + 32] = p1;
    __syncwarp();

    float o0 = 0.f, o1 = 0.f;
    for (int dp = 0; dp < DD; dp++) {
        float pv = pool[warp][dp];
        o0 = fmaf(pv, Wo[dp * DD + lane],      o0);
        o1 = fmaf(pv, Wo[dp * DD + lane + 32], o1);
    }
    g_outp[q * DD + lane] = o0;
    g_outp[q * DD + lane + 32] = o1;
    atomicAdd(&acc[lane], o0);
    atomicAdd(&acc[lane + 32], o1);
    atomicAdd(&acc[64 + lane], o0 * o0);
    atomicAdd(&acc[64 + lane + 32], o1 * o1);
    __syncthreads();
    if (tid < 128) atomicAdd(&g_stats[384 + tid], acc[tid]);
}

// ---------------- K5a: finalize out BN ----------------
__global__ void k_fout(const float* __restrict__ gout, const float* __restrict__ beout) {
    int d = threadIdx.x;
    float n = (float)NQ;
    float s1 = g_stats[384 + d], s2 = g_stats[448 + d];
    float mu = s1 / n, var = s2 / n - mu * mu;
    float a = gout[d] * rsqrtf(var + EPSV);
    g_bn[384 + d] = a; g_bn[448 + d] = beout[d] - mu * a;
}

// ---------------- K5: fused epilogue (coalesced), y transposed [B,D,M] ----------------
__global__ __launch_bounds__(256) void k_final(float* __restrict__ out) {
    __shared__ float sm[32][65];
    int blk = blockIdx.x;             // 256 blocks: b = blk>>7, m-tile = blk&127
    int b = blk >> 7;
    int m0 = (blk & 127) * 32;
    int warp = threadIdx.x >> 5, lane = threadIdx.x & 31;
#pragma unroll
    for (int i = 0; i < 4; i++) {
        int r = warp * 4 + i;                  // row within m-tile
        int q = b * MM + m0 + r;
#pragma unroll
        for (int h = 0; h < 2; h++) {
            int d = lane + 32 * h;
            float o  = fmaxf(fmaf(g_bn[384 + d], g_outp[q * DD + d], g_bn[448 + d]), 0.f);
            float v1 = fmaf(g_bn[128 + d], g_sc1[q * DD + d], g_bn[192 + d]);
            float v2 = fmaf(g_bn[256 + d], g_sc2[q * DD + d], g_bn[320 + d]);
            sm[r][d] = fmaxf(o + v1 + v2, 0.f);
        }
    }
    __syncthreads();
#pragma unroll
    for (int i = 0; i < 8; i++) {
        int d = warp * 8 + i;
        out[24576 + ((size_t)(b * DD + d)) * MM + m0 + lane] = sm[lane][d];
    }
}

// ---------------- launch ----------------
extern "C" void kernel_launch(void* const* d_in, const int* in_sizes, int n_in,
                              void* d_out, int out_size) {
    const float* xyz    = (const float*)d_in[0];
    const float* feats  = (const float*)d_in[1];
    const int*   sidx   = (const int*)  d_in[2];
    const float* Wpos   = (const float*)d_in[3];
    const float* bpos   = (const float*)d_in[4];
    const float* gpos   = (const float*)d_in[5];
    const float* bepos  = (const float*)d_in[6];
    const float* Wfeat  = (const float*)d_in[7];
    const float* bfeat  = (const float*)d_in[8];
    const float* gfeat  = (const float*)d_in[9];
    const float* befeat = (const float*)d_in[10];
    const float* Wscore = (const float*)d_in[11];
    const float* Wout   = (const float*)d_in[12];
    const float* gout   = (const float*)d_in[13];
    const float* beout  = (const float*)d_in[14];
    const float* Wsc1   = (const float*)d_in[15];
    const float* gsc1   = (const float*)d_in[16];
    const float* besc1  = (const float*)d_in[17];
    const float* Wsc2   = (const float*)d_in[18];
    const float* gsc2   = (const float*)d_in[19];
    const float* besc2  = (const float*)d_in[20];
    float* out = (float*)d_out;

    k_init<<<32, 256>>>(xyz, sidx, out);
    k_prep<<<(BB * NN) / 256, 256>>>(xyz);
    dim3 tb(32, 32);
    k_transpose<<<dim3(NN / 32, BB), tb>>>(feats);
    k_knn<<<NQ / 16, 512>>>(sidx);
    k_stage2<<<NQ / 8, 256>>>(xyz, sidx, Wpos, bpos, Wfeat, bfeat, Wsc1, Wsc2);
    k_fstats1<<<1, 64>>>(gpos, bepos, gfeat, befeat, gsc1, besc1, gsc2, besc2);
    k_attn<<<NQ / 8, 256>>>(Wscore, Wout);
    k_fout<<<1, 64>>>(gout, beout);
    k_final<<<256, 256>>>(out);
}